// round 8
// baseline (speedup 1.0000x reference)
#include <cuda_runtime.h>

// VariantCoeLinear1d: 1D Rusanov FV solver, 128 rows x 2048 pts x 256 steps.
// One CTA per row (128 CTAs, single wave). 512 threads x 4 register points
// (occ 25%, the R7 win).
//
// R8: triple (u,f,|f'|) float4 halo exchange with STS drain-distance control:
// the BOUNDARY pair (u[0],u[3]) is poly-packed FIRST, its triples published
// to SMEM immediately, and the interior pack + interior interfaces/updates
// (~45 instrs) run between the STS and the barrier, so BAR.SYNC's STS-drain
// penalty (+36cyc/in-flight STS at nw>=8, the R6 killer) is fully hidden.
// Halo poly recompute deleted: -1 POLY_PACK/thread/step vs R7.

#define BATCH 128
#define NPTS  2048
#define STEPS 256
#define TPB   512
#define PPT   4   // TPB*PPT == NPTS

typedef unsigned long long u64;

static __device__ __forceinline__ u64 pk(float lo, float hi) {
    u64 r; asm("mov.b64 %0,{%1,%2};" : "=l"(r) : "f"(lo), "f"(hi)); return r;
}
static __device__ __forceinline__ void upk(float& lo, float& hi, u64 v) {
    asm("mov.b64 {%0,%1},%2;" : "=f"(lo), "=f"(hi) : "l"(v));
}
static __device__ __forceinline__ u64 f2fma(u64 a, u64 b, u64 c) {
    u64 d; asm("fma.rn.f32x2 %0,%1,%2,%3;" : "=l"(d) : "l"(a), "l"(b), "l"(c)); return d;
}
static __device__ __forceinline__ u64 f2mul(u64 a, u64 b) {
    u64 d; asm("mul.rn.f32x2 %0,%1,%2;" : "=l"(d) : "l"(a), "l"(b)); return d;
}

// fh = (f_l + f_r) - max(a_l,a_r) * (u_r - u_l)   (0.5 folded into HL)
static __device__ __forceinline__ float iface(float ul, float fl, float al,
                                              float ur, float fr, float ar) {
    float am = fmaxf(al, ar);
    return fmaf(-am, ur - ul, fl + fr);
}

// Horner pack: f and |f'| for two points, 10 f32x2 ops.
#define POLY_PACK(U, FLO, FHI, ALO, AHI)                                   \
    do {                                                                   \
        u64 _u2 = f2mul(U, U);                                             \
        u64 _t  = f2fma(CB6, _u2, CB4);                                    \
        _t      = f2fma(_t, U, CB3);                                       \
        _t      = f2fma(_t, U, CB2);                                       \
        _t      = f2fma(_t, U, CB1);                                       \
        u64 _F  = f2mul(_t, U);                                            \
        u64 _s  = f2fma(CA5, _u2, CA3);                                    \
        _s      = f2fma(_s, U, CA2);                                       \
        _s      = f2fma(_s, U, CA1);                                       \
        _s      = f2fma(_s, U, CA0);                                       \
        u64 _A  = _s & ABSM;                                               \
        upk(FLO, FHI, _F);                                                 \
        upk(ALO, AHI, _A);                                                 \
    } while (0)

__global__ void __launch_bounds__(TPB, 1)
vcl_kernel(const float* __restrict__ init, float* __restrict__ out)
{
    // double-buffered boundary triples {u, f, a, pad}
    __shared__ float4 sL[2][TPB];   // thread t's FIRST point
    __shared__ float4 sR[2][TPB];   // thread t's LAST point

    const int row  = blockIdx.x;
    const int tid  = threadIdx.x;
    const int base = tid * PPT;
    const int tl   = (tid > 0) ? tid - 1 : 0;              // edge dummies:
    const int tr   = (tid < TPB - 1) ? tid + 1 : TPB - 1;  // overwritten by BC
    const float HL = 0.5f * (float)(0.002 / (10.0 / 2048.0));  // 0.5*dt/dx

    const double c = 0.1 / 12.0;   // beta/12
    const u64 CB1 = pk(1.5f, 1.5f);
    const u64 CB2 = pk((float)(0.75 * c),        (float)(0.75 * c));
    const u64 CB3 = pk((float)(-0.5 - 2.0 * c),  (float)(-0.5 - 2.0 * c));
    const u64 CB4 = pk((float)(1.5 * c),         (float)(1.5 * c));
    const u64 CB6 = pk((float)(-0.25 * c),       (float)(-0.25 * c));
    const u64 CA0 = pk(1.5f, 1.5f);
    const u64 CA1 = pk((float)(1.5 * c),         (float)(1.5 * c));
    const u64 CA2 = pk((float)(-1.5 - 6.0 * c),  (float)(-1.5 - 6.0 * c));
    const u64 CA3 = pk((float)(6.0 * c),         (float)(6.0 * c));
    const u64 CA5 = pk((float)(-1.5 * c),        (float)(-1.5 * c));
    const u64 ABSM = 0x7fffffff7fffffffULL;

    float u0, u1, u2, u3;
    {
        const float4* ip = reinterpret_cast<const float4*>(init + (size_t)row * NPTS + base);
        float4 a0 = ip[0];
        u0 = a0.x; u1 = a0.y; u2 = a0.z; u3 = a0.w;
        float4* o0 = reinterpret_cast<float4*>(out + (size_t)row * NPTS + base);
        __stcs(o0, a0);
    }

    float4* op = reinterpret_cast<float4*>(out + ((size_t)BATCH + row) * NPTS + base);
    const size_t ostride = (size_t)BATCH * NPTS / 4;

    #pragma unroll 2
    for (int s = 1; s < STEPS; ++s) {
        const int b = s & 1;

        // ---- boundary pair FIRST; publish triples immediately ----
        float f0, f3, a0, a3;
        {
            u64 U = pk(u0, u3);
            POLY_PACK(U, f0, f3, a0, a3);
        }
        sL[b][tid] = make_float4(u0, f0, a0, 0.0f);
        sR[b][tid] = make_float4(u3, f3, a3, 0.0f);

        // ---- interior pack + interior interfaces/updates (STS drain gap) ----
        float f1, f2, a1, a2;
        {
            u64 U = pk(u1, u2);
            POLY_PACK(U, f1, f2, a1, a2);
        }
        float fh1 = iface(u0, f0, a0, u1, f1, a1);
        float fh2 = iface(u1, f1, a1, u2, f2, a2);
        float fh3 = iface(u2, f2, a2, u3, f3, a3);
        float un1 = fmaf(-HL, fh2 - fh1, u1);
        float un2 = fmaf(-HL, fh3 - fh2, u2);

        // ---- barrier (STS long since drained) ----
        __syncthreads();

        float4 nl = sR[b][tl];   // left neighbor's last-point triple
        float4 nr = sL[b][tr];   // right neighbor's first-point triple

        float fh0 = iface(nl.x, nl.y, nl.z, u0, f0, a0);
        float fh4 = iface(u3, f3, a3, nr.x, nr.y, nr.z);
        float un0 = fmaf(-HL, fh1 - fh0, u0);
        float un3 = fmaf(-HL, fh4 - fh3, u3);

        if (tid == 0)       un0 = un1;   // outflow BC
        if (tid == TPB - 1) un3 = un2;

        // ---- stream frame (write-only; evict-first) ----
        __stcs(op, make_float4(un0, un1, un2, un3));
        op += ostride;

        u0 = un0; u1 = un1; u2 = un2; u3 = un3;
    }
}

extern "C" void kernel_launch(void* const* d_in, const int* in_sizes, int n_in,
                              void* d_out, int out_size) {
    const float* init = (const float*)d_in[0];   // [128, 2048] fp32
    // d_in[1] = stepnum (int32) — fixed at 256 by the problem spec
    float* out = (float*)d_out;                  // [256, 128, 2048] fp32
    vcl_kernel<<<BATCH, TPB>>>(init, out);
}